// round 10
// baseline (speedup 1.0000x reference)
#include <cuda_runtime.h>
#include <math.h>

#define B_   4
#define Q_   64
#define H_   4096
#define NH_  32
#define KVH_ 8
#define HD_  128
#define P_   4096
#define M_   256            // B*Q
#define KVLEN 4160          // P+Q

// ---------------- scratch ----------------
__device__ float g_qraw [M_ * NH_ * HD_];
__device__ float g_qraw2[M_ * NH_ * HD_];
__device__ float g_kraw [M_ * KVH_ * HD_];
__device__ float g_kraw2[M_ * KVH_ * HD_];
__device__ float g_vraw [M_ * KVH_ * HD_];
__device__ float g_vraw2[M_ * KVH_ * HD_];
__device__ float g_q  [B_ * NH_ * Q_ * HD_];
__device__ float g_kn [B_ * KVH_ * Q_ * HD_];
__device__ float g_vn [B_ * KVH_ * Q_ * HD_];
__device__ float g_ctx[M_ * NH_ * HD_];
__device__ float g_actx[2 * B_ * NH_ * Q_ * HD_];
__device__ float g_am  [2 * B_ * NH_ * Q_];
__device__ float g_al  [2 * B_ * NH_ * Q_];

// ---------------- tf32 helpers ----------------
__device__ __forceinline__ unsigned f2u_tf32(float x) {
    unsigned r; asm("cvt.rna.tf32.f32 %0, %1;" : "=r"(r) : "f"(x)); return r;
}
__device__ __forceinline__ float f_tf32(float x) { return __uint_as_float(f2u_tf32(x)); }
__device__ __forceinline__ unsigned fu(float x) { return __float_as_uint(x); }
__device__ __forceinline__ unsigned rna_u(unsigned x) {
    unsigned r; asm("cvt.rna.tf32.f32 %0, %1;" : "=r"(r) : "f"(__uint_as_float(x))); return r;
}
__device__ __forceinline__ float4 round4(float4 v) {
    return make_float4(f_tf32(v.x), f_tf32(v.y), f_tf32(v.z), f_tf32(v.w));
}

__device__ __forceinline__ void mma_tf32(float& c0, float& c1, float& c2, float& c3,
                                         unsigned a0, unsigned a1, unsigned a2, unsigned a3,
                                         unsigned b0, unsigned b1) {
    asm volatile(
        "mma.sync.aligned.m16n8k8.row.col.f32.tf32.tf32.f32 "
        "{%0,%1,%2,%3}, {%4,%5,%6,%7}, {%8,%9}, {%0,%1,%2,%3};\n"
        : "+f"(c0), "+f"(c1), "+f"(c2), "+f"(c3)
        : "r"(a0), "r"(a1), "r"(a2), "r"(a3), "r"(b0), "r"(b1));
}

__device__ __forceinline__ void cp16(void* smem_dst, const void* gmem_src) {
    unsigned ds = (unsigned)__cvta_generic_to_shared(smem_dst);
    asm volatile("cp.async.cg.shared.global [%0], [%1], 16;\n" :: "r"(ds), "l"(gmem_src));
}

// ================= pipelined tf32 GEMM: BM64 x BN128 x BK32, 256 thr, 3-stage =================
#define GA_S 36
#define GB_S 136
#define G_STAGE_FLOATS (64 * GA_S + 32 * GB_S)       // 6656
#define GEMM_SMEM_FLOATS (3 * G_STAGE_FLOATS)        // 19968
#define GEMM_SMEM_BYTES  (GEMM_SMEM_FLOATS * 4)      // 79872

__device__ __forceinline__ void gemm_issue(
    const float* __restrict__ Abase, const float* __restrict__ Wbase,
    int lda, int N, int k0, float* sA, float* sB,
    int arow, int ac4, int brow, int bc4)
{
    cp16(sA + arow * GA_S + ac4,        Abase + arow * lda + k0 + ac4);
    cp16(sA + (arow + 32) * GA_S + ac4, Abase + (arow + 32) * lda + k0 + ac4);
    #pragma unroll
    for (int i = 0; i < 4; i++)
        cp16(sB + (brow + (i << 3)) * GB_S + bc4, Wbase + (k0 + brow + (i << 3)) * N + bc4);
    asm volatile("cp.async.commit_group;\n");
}

template<bool ATOMIC>
__device__ __forceinline__ void gemm_pipe(
    const float* __restrict__ A, int lda,
    const float* __restrict__ W, float* __restrict__ C,
    int N, int kLen, int m0, int n0, float* sm)
{
    float* sAs[3] = { sm, sm + G_STAGE_FLOATS, sm + 2 * G_STAGE_FLOATS };
    float* sBs[3] = { sm + 64 * GA_S, sm + G_STAGE_FLOATS + 64 * GA_S,
                      sm + 2 * G_STAGE_FLOATS + 64 * GA_S };

    const int tid = threadIdx.x;
    const int warp = tid >> 5, lane = tid & 31;
    const int mw = warp >> 2, nw = warp & 3;
    const int g = lane >> 2, t = lane & 3;

    const int arow = tid >> 3, ac4 = (tid & 7) << 2;
    const int brow = tid >> 5, bc4 = (tid & 31) << 2;

    const float* Abase = A + m0 * lda;
    const float* Wbase = W + n0;

    float acc[2][4][4];
    #pragma unroll
    for (int mt = 0; mt < 2; mt++)
        #pragma unroll
        for (int nt = 0; nt < 4; nt++)
            #pragma unroll
            for (int i = 0; i < 4; i++) acc[mt][nt][i] = 0.f;

    const int ntiles = kLen >> 5;
    gemm_issue(Abase, Wbase, lda, N, 0,  sAs[0], sBs[0], arow, ac4, brow, bc4);
    gemm_issue(Abase, Wbase, lda, N, 32, sAs[1], sBs[1], arow, ac4, brow, bc4);

    for (int tI = 0; tI < ntiles; tI++) {
        if (tI + 2 < ntiles) {
            gemm_issue(Abase, Wbase, lda, N, (tI + 2) << 5,
                       sAs[(tI + 2) % 3], sBs[(tI + 2) % 3], arow, ac4, brow, bc4);
            asm volatile("cp.async.wait_group 2;\n");
        } else if (tI + 1 < ntiles) {
            asm volatile("cp.async.wait_group 1;\n");
        } else {
            asm volatile("cp.async.wait_group 0;\n");
        }
        __syncthreads();

        float* sA = sAs[tI % 3];
        float* sB = sBs[tI % 3];

        #pragma unroll
        for (int ks = 0; ks < 4; ks++) {
            const int k0 = ks << 3;
            unsigned a[2][4], b[4][2];
            #pragma unroll
            for (int mt = 0; mt < 2; mt++) {
                const int r = (mw << 5) + (mt << 4) + g;
                a[mt][0] = rna_u(fu(sA[r * GA_S + k0 + t]));
                a[mt][1] = rna_u(fu(sA[(r + 8) * GA_S + k0 + t]));
                a[mt][2] = rna_u(fu(sA[r * GA_S + k0 + t + 4]));
                a[mt][3] = rna_u(fu(sA[(r + 8) * GA_S + k0 + t + 4]));
            }
            #pragma unroll
            for (int nt = 0; nt < 4; nt++) {
                const int cn = (nw << 5) + (nt << 3) + g;
                b[nt][0] = rna_u(fu(sB[(k0 + t) * GB_S + cn]));
                b[nt][1] = rna_u(fu(sB[(k0 + t + 4) * GB_S + cn]));
            }
            #pragma unroll
            for (int mt = 0; mt < 2; mt++)
                #pragma unroll
                for (int nt = 0; nt < 4; nt++)
                    mma_tf32(acc[mt][nt][0], acc[mt][nt][1], acc[mt][nt][2], acc[mt][nt][3],
                             a[mt][0], a[mt][1], a[mt][2], a[mt][3], b[nt][0], b[nt][1]);
        }
        __syncthreads();
    }

    #pragma unroll
    for (int mt = 0; mt < 2; mt++) {
        const int r = m0 + (mw << 5) + (mt << 4) + g;
        #pragma unroll
        for (int nt = 0; nt < 4; nt++) {
            const int cn = n0 + (nw << 5) + (nt << 3) + (t << 1);
            if (ATOMIC) {
                atomicAdd(C + r * N + cn,           acc[mt][nt][0]);
                atomicAdd(C + r * N + cn + 1,       acc[mt][nt][1]);
                atomicAdd(C + (r + 8) * N + cn,     acc[mt][nt][2]);
                atomicAdd(C + (r + 8) * N + cn + 1, acc[mt][nt][3]);
            } else {
                *(float2*)(C + r * N + cn)       = make_float2(acc[mt][nt][0], acc[mt][nt][1]);
                *(float2*)(C + (r + 8) * N + cn) = make_float2(acc[mt][nt][2], acc[mt][nt][3]);
            }
        }
    }
}

// fused QKV projection, split-K = 2 (partials summed in lnrope)
__global__ __launch_bounds__(256, 2) void gemm_qkv(
    const float* __restrict__ hs,
    const float* __restrict__ Wq, const float* __restrict__ Wk, const float* __restrict__ Wv,
    float* __restrict__ qraw, float* __restrict__ kraw, float* __restrict__ vraw,
    float* __restrict__ qraw2, float* __restrict__ kraw2, float* __restrict__ vraw2)
{
    extern __shared__ float smg[];
    const int x = blockIdx.x;
    const int kw = blockIdx.z;
    const float* W; float* C; int N, nb;
    if (x < 32)      { W = Wq; C = kw ? qraw2 : qraw; N = 4096; nb = x; }
    else if (x < 40) { W = Wk; C = kw ? kraw2 : kraw; N = 1024; nb = x - 32; }
    else             { W = Wv; C = kw ? vraw2 : vraw; N = 1024; nb = x - 40; }
    gemm_pipe<false>(hs + kw * 2048, H_, W + kw * 2048 * N, C, N, 2048,
                     blockIdx.y << 6, nb << 7, smg);
}

// out projection, split-K = 2, atomic accumulate into pre-zeroed out
__global__ __launch_bounds__(256, 2) void gemm_out(
    const float* __restrict__ A, const float* __restrict__ W, float* __restrict__ out)
{
    extern __shared__ float smg[];
    const int kw = blockIdx.z;
    const int KH = (NH_ * HD_) / 2;
    gemm_pipe<true>(A + kw * KH, NH_ * HD_, W + kw * KH * H_, out,
                    H_, KH, blockIdx.y << 6, blockIdx.x << 7, smg);
}

// ---------------- LN + RoPE + transpose (sums split-K partials) ----------------
__global__ __launch_bounds__(128) void lnrope_kernel(
    const float* __restrict__ qraw, const float* __restrict__ qraw2,
    const float* __restrict__ kraw, const float* __restrict__ kraw2,
    const float* __restrict__ vraw, const float* __restrict__ vraw2,
    const float* __restrict__ qlw, const float* __restrict__ qlb,
    const float* __restrict__ klw, const float* __restrict__ klb,
    const int* __restrict__ pos_ids,
    float* __restrict__ qout, float* __restrict__ knout, float* __restrict__ vnout)
{
    const int blk = blockIdx.x;
    const int bq = blk / 48;
    const int t  = blk - bq * 48;
    const int b  = bq >> 6, qi = bq & 63;
    const int d  = threadIdx.x;

    if (t >= 40) {
        const int vh = t - 40;
        const int i = bq * (KVH_ * HD_) + vh * HD_ + d;
        vnout[((b * KVH_ + vh) * Q_ + qi) * HD_ + d] = vraw[i] + vraw2[i];
        return;
    }

    __shared__ float row[128];
    __shared__ float red[4];

    float x, w, bb;
    const bool isq = (t < 32);
    if (isq) {
        const int i = bq * (NH_ * HD_) + t * HD_ + d;
        x  = qraw[i] + qraw2[i];
        w  = qlw[t * HD_ + d];
        bb = qlb[t * HD_ + d];
    } else {
        const int kh = t - 32;
        const int i = bq * (KVH_ * HD_) + kh * HD_ + d;
        x  = kraw[i] + kraw2[i];
        w  = klw[kh * HD_ + d];
        bb = klb[kh * HD_ + d];
    }

    const int lane = d & 31, wid = d >> 5;

    float s = x;
    #pragma unroll
    for (int o = 16; o; o >>= 1) s += __shfl_xor_sync(0xffffffffu, s, o);
    if (lane == 0) red[wid] = s;
    __syncthreads();
    const float mean = (red[0] + red[1] + red[2] + red[3]) * (1.f / 128.f);
    const float dx = x - mean;
    float s2 = dx * dx;
    __syncthreads();
    #pragma unroll
    for (int o = 16; o; o >>= 1) s2 += __shfl_xor_sync(0xffffffffu, s2, o);
    if (lane == 0) red[wid] = s2;
    __syncthreads();
    const float var = (red[0] + red[1] + red[2] + red[3]) * (1.f / 128.f);

    const float xn = dx * rsqrtf(var + 1e-5f) * w + bb;
    row[d] = xn;
    __syncthreads();
    const float partner = row[d ^ 64];

    const int j = d & 63;
    const float inv = (float)exp(-(double)(2 * j) * (1.0 / 128.0) * 9.210340371976184);
    const float ang = (float)pos_ids[b * Q_ + qi] * inv;
    const float c = cosf(ang), sn = sinf(ang);
    const float rot = (d < 64) ? -partner : partner;
    const float outv = xn * c + rot * sn;

    if (isq)
        qout[((b * NH_ + t) * Q_ + qi) * HD_ + d] = outv * 0.08838834764831845f;
    else
        knout[((b * KVH_ + (t - 32)) * Q_ + qi) * HD_ + d] = outv;
}

// ---------------- flash attention v4: loader-side tf32 conversion, 1 barrier/chunk ----------------
// grid = (B*NH, 2), 128 threads = 4 warps. chunk=32, KV split=2 (2080 keys = 65 chunks).
#define CHK   32
#define NCHK  65
#define SPLIT_KEYS 2080
#define SQ_S  132
#define SKV_S 132
#define SS2_S 36
#define AOFF_Q   0
#define AOFF_K0  (64 * SQ_S)                 // 8448
#define AOFF_K1  (AOFF_K0 + CHK * SKV_S)     // 12672
#define AOFF_V0  (AOFF_K1 + CHK * SKV_S)     // 16896
#define AOFF_V1  (AOFF_V0 + CHK * SKV_S)     // 21120
#define AOFF_S   (AOFF_V1 + CHK * SKV_S)     // 25344
#define ATT4_FLOATS (AOFF_S + 64 * SS2_S)    // 27648
#define ATT4_BYTES  (ATT4_FLOATS * 4)        // 110592

__global__ __launch_bounds__(128, 2) void attn_kernel4(
    const float* __restrict__ past_k, const float* __restrict__ past_v,
    const float* __restrict__ mask,
    const float* __restrict__ qg, const float* __restrict__ kn,
    const float* __restrict__ vn,
    float* __restrict__ actx, float* __restrict__ am, float* __restrict__ al)
{
    extern __shared__ float sm[];
    float* sQ  = sm + AOFF_Q;
    float* sKb[2] = { sm + AOFF_K0, sm + AOFF_K1 };
    float* sVb[2] = { sm + AOFF_V0, sm + AOFF_V1 };
    float* sS  = sm + AOFF_S;

    const int tid = threadIdx.x;
    const int bh = blockIdx.x;           // b*32 + h
    const int split = blockIdx.y;
    const int b = bh >> 5;
    const int h = bh & 31;
    const int kvh = h >> 2;

    const int warp = tid >> 5, lane = tid & 31;
    const int g = lane >> 2, t = lane & 3;
    const int r0 = (warp << 4) + g;      // first owned row; second is r0+8

    const int lrow = tid >> 5, lc4 = (tid & 31) << 2;   // loader: rows lrow+4i, one float4 each

    // ---- load Q (tf32-rounded, row-major) ----
    const float* qbase = qg + (b * NH_ + h) * Q_ * HD_;
    #pragma unroll
    for (int i = 0; i < 16; i++) {
        const int row = lrow + (i << 2);
        *(float4*)(sQ + row * SQ_S + lc4) = round4(*(const float4*)(qbase + row * HD_ + lc4));
    }

    float m0r = -1e30f, m1r = -1e30f, l0r = 0.f, l1r = 0.f;

    float o[16][4];
    #pragma unroll
    for (int nt = 0; nt < 16; nt++)
        #pragma unroll
        for (int i = 0; i < 4; i++) o[nt][i] = 0.f;

    const int kvoff  = ((b * KVH_ + kvh) * P_) * HD_;
    const int newoff = (b * KVH_ + kvh) * Q_ * HD_;
    const int keybase0 = split * SPLIT_KEYS;

    // ---- prologue: LDG chunk 0 into registers ----
    float4 rK[8], rV[8];
    {
        const int base = keybase0;
        const float* Kc = (base < P_) ? past_k + kvoff + base * HD_ : kn + newoff + (base - P_) * HD_;
        const float* Vc = (base < P_) ? past_v + kvoff + base * HD_ : vn + newoff + (base - P_) * HD_;
        #pragma unroll
        for (int i = 0; i < 8; i++) {
            const int row = lrow + (i << 2);
            rK[i] = *(const float4*)(Kc + row * HD_ + lc4);
            rV[i] = *(const float4*)(Vc + row * HD_ + lc4);
        }
    }

    for (int chunk = 0; chunk < NCHK; chunk++) {
        // ---- convert (rna, once per element) + store current chunk to smem ----
        float* dK = sKb[chunk & 1];
        float* dV = sVb[chunk & 1];
        #pragma unroll
        for (int i = 0; i < 8; i++) {
            const int row = lrow + (i << 2);
            *(float4*)(dK + row * SKV_S + lc4) = round4(rK[i]);
            *(float4*)(dV + row * SKV_S + lc4) = round4(rV[i]);
        }
        __syncthreads();

        // ---- issue LDG for next chunk (latency hidden under MMA phase) ----
        if (chunk + 1 < NCHK) {
            const int base = keybase0 + (chunk + 1) * CHK;
            const float* Kc = (base < P_) ? past_k + kvoff + base * HD_ : kn + newoff + (base - P_) * HD_;
            const float* Vc = (base < P_) ? past_v + kvoff + base * HD_ : vn + newoff + (base - P_) * HD_;
            #pragma unroll
            for (int i = 0; i < 8; i++) {
                const int row = lrow + (i << 2);
                rK[i] = *(const float4*)(Kc + row * HD_ + lc4);
                rV[i] = *(const float4*)(Vc + row * HD_ + lc4);
            }
        }

        float* sK = dK;
        float* sV = dV;

        // ---- S = Q K^T : warp tile 16x32, frags pre-rounded (no cvt) ----
        float sc[4][4];
        #pragma unroll
        for (int nt = 0; nt < 4; nt++)
            #pragma unroll
            for (int i = 0; i < 4; i++) sc[nt][i] = 0.f;

        #pragma unroll
        for (int ks = 0; ks < 16; ks++) {
            const int k0 = ks << 3;
            unsigned a0 = fu(sQ[r0 * SQ_S + k0 + t]);
            unsigned a1 = fu(sQ[(r0 + 8) * SQ_S + k0 + t]);
            unsigned a2 = fu(sQ[r0 * SQ_S + k0 + t + 4]);
            unsigned a3 = fu(sQ[(r0 + 8) * SQ_S + k0 + t + 4]);
            #pragma unroll
            for (int nt = 0; nt < 4; nt++) {
                const int cn = (nt << 3) + g;
                unsigned b0 = fu(sK[cn * SKV_S + k0 + t]);
                unsigned b1 = fu(sK[cn * SKV_S + k0 + t + 4]);
                mma_tf32(sc[nt][0], sc[nt][1], sc[nt][2], sc[nt][3], a0, a1, a2, a3, b0, b1);
            }
        }

        // ---- mask (whole chunk masked iff base >= P_; split boundary aligns) ----
        const int base = keybase0 + chunk * CHK;
        if (base >= P_) {
            const float* mr0 = mask + (b * Q_ + r0) * KVLEN + base;
            const float* mr1 = mask + (b * Q_ + r0 + 8) * KVLEN + base;
            #pragma unroll
            for (int nt = 0; nt < 4; nt++) {
                const float2 mv0 = *(const float2*)(mr0 + (nt << 3) + (t << 1));
                const float2 mv1 = *(const float2*)(mr1 + (nt << 3) + (t << 1));
                sc[nt][0] += mv0.x; sc[nt][1] += mv0.y;
                sc[nt][2] += mv1.x; sc[nt][3] += mv1.y;
            }
        }

        // ---- register softmax ----
        float cm0 = -1e30f, cm1 = -1e30f;
        #pragma unroll
        for (int nt = 0; nt < 4; nt++) {
            cm0 = fmaxf(cm0, fmaxf(sc[nt][0], sc[nt][1]));
            cm1 = fmaxf(cm1, fmaxf(sc[nt][2], sc[nt][3]));
        }
        cm0 = fmaxf(cm0, __shfl_xor_sync(0xffffffffu, cm0, 1));
        cm0 = fmaxf(cm0, __shfl_xor_sync(0xffffffffu, cm0, 2));
        cm1 = fmaxf(cm1, __shfl_xor_sync(0xffffffffu, cm1, 1));
        cm1 = fmaxf(cm1, __shfl_xor_sync(0xffffffffu, cm1, 2));

        const float mn0 = fmaxf(m0r, cm0);
        const float mn1 = fmaxf(m1r, cm1);
        const float scl0 = __expf(m0r - mn0);
        const float scl1 = __expf(m1r - mn1);

        float sum0 = 0.f, sum1 = 0.f;
        #pragma unroll
        for (int nt = 0; nt < 4; nt++) {
            float p;
            p = f_tf32(__expf(sc[nt][0] - mn0)); sc[nt][0] = p; sum0 += p;
            p = f_tf32(__expf(sc[nt][1] - mn0)); sc[nt][1] = p; sum0 += p;
            p = f_tf32(__expf(sc[nt][2] - mn1)); sc[nt][2] = p; sum1 += p;
            p = f_tf32(__expf(sc[nt][3] - mn1)); sc[nt][3] = p; sum1 += p;
        }
        sum0 += __shfl_xor_sync(0xffffffffu, sum0, 1);
        sum0 += __shfl_xor_sync(0xffffffffu, sum0, 2);
        sum1 += __shfl_xor_sync(0xffffffffu, sum1, 1);
        sum1 += __shfl_xor_sync(0xffffffffu, sum1, 2);

        l0r = l0r * scl0 + sum0;  m0r = mn0;
        l1r = l1r * scl1 + sum1;  m1r = mn1;

        // ---- rescale ctx frags ----
        #pragma unroll
        for (int nt = 0; nt < 16; nt++) {
            o[nt][0] *= scl0; o[nt][1] *= scl0;
            o[nt][2] *= scl1; o[nt][3] *= scl1;
        }

        // ---- store P (warp-local rows) ----
        #pragma unroll
        for (int nt = 0; nt < 4; nt++) {
            *(float2*)(sS + r0 * SS2_S + (nt << 3) + (t << 1))       = make_float2(sc[nt][0], sc[nt][1]);
            *(float2*)(sS + (r0 + 8) * SS2_S + (nt << 3) + (t << 1)) = make_float2(sc[nt][2], sc[nt][3]);
        }
        __syncwarp();

        // ---- ctx += P @ V : warp tile 16x128, k=32 ----
        #pragma unroll
        for (int ks = 0; ks < 4; ks++) {
            const int k0 = ks << 3;
            unsigned a0 = fu(sS[r0 * SS2_S + k0 + t]);
            unsigned a1 = fu(sS[(r0 + 8) * SS2_S + k0 + t]);
            unsigned a2 = fu(sS[r0 * SS2_S + k0 + t + 4]);
            unsigned a3 = fu(sS[(r0 + 8) * SS2_S + k0 + t + 4]);
            #pragma unroll
            for (int nt = 0; nt < 16; nt++) {
                const int cn = (nt << 3) + g;
                unsigned b0 = fu(sV[(k0 + t) * SKV_S + cn]);
                unsigned b1 = fu(sV[(k0 + t + 4) * SKV_S + cn]);
                mma_tf32(o[nt][0], o[nt][1], o[nt][2], o[nt][3], a0, a1, a2, a3, b0, b1);
            }
        }
        // no trailing barrier: next iteration's STS targets the other buffer;
        // buffer reuse two chunks later is fenced by the intervening __syncthreads.
    }

    // ---- epilogue: write unnormalized acc + (m, l) ----
    float* abase = actx + ((size_t)(split * (B_ * NH_) + bh) * Q_) * HD_;
    #pragma unroll
    for (int nt = 0; nt < 16; nt++) {
        const int cn = (nt << 3) + (t << 1);
        *(float2*)(abase + r0 * HD_ + cn)       = make_float2(o[nt][0], o[nt][1]);
        *(float2*)(abase + (r0 + 8) * HD_ + cn) = make_float2(o[nt][2], o[nt][3]);
    }
    if (t == 0) {
        const int sidx = (split * (B_ * NH_) + bh) * Q_;
        am[sidx + r0]     = m0r;  al[sidx + r0]     = l0r;
        am[sidx + r0 + 8] = m1r;  al[sidx + r0 + 8] = l1r;
    }
}

// merge the two attention splits -> ctx[b][qi][h][d]
__global__ __launch_bounds__(128) void attn_merge(
    const float* __restrict__ actx, const float* __restrict__ am,
    const float* __restrict__ al, float* __restrict__ ctx)
{
    const int bh = blockIdx.x;
    const int b = bh >> 5, h = bh & 31;
    const int d = threadIdx.x;
    const int q0 = blockIdx.y << 2;

    #pragma unroll
    for (int k = 0; k < 4; k++) {
        const int qi = q0 + k;
        const float m0 = am[bh * Q_ + qi];
        const float m1 = am[(B_ * NH_ + bh) * Q_ + qi];
        const float mm = fmaxf(m0, m1);
        const float w0 = __expf(m0 - mm), w1 = __expf(m1 - mm);
        const float den = w0 * al[bh * Q_ + qi] + w1 * al[(B_ * NH_ + bh) * Q_ + qi];
        const float inv = 1.0f / den;
        const float a0 = actx[((size_t)bh * Q_ + qi) * HD_ + d];
        const float a1 = actx[((size_t)(B_ * NH_ + bh) * Q_ + qi) * HD_ + d];
        ctx[((b * Q_ + qi) * NH_ + h) * HD_ + d] = (w0 * a0 + w1 * a1) * inv;
    }
}

// ---------------- launch ----------------
extern "C" void kernel_launch(void* const* d_in, const int* in_sizes, int n_in,
                              void* d_out, int out_size)
{
    const float* hs   = (const float*)d_in[0];
    const float* Wq   = (const float*)d_in[1];
    const float* Wk   = (const float*)d_in[2];
    const float* Wv   = (const float*)d_in[3];
    const float* Wo   = (const float*)d_in[4];
    const float* qlw  = (const float*)d_in[5];
    const float* qlb  = (const float*)d_in[6];
    const float* klw  = (const float*)d_in[7];
    const float* klb  = (const float*)d_in[8];
    const float* pk   = (const float*)d_in[9];
    const float* pv   = (const float*)d_in[10];
    const float* mask = (const float*)d_in[11];
    const int*   pos  = (const int*)d_in[12];
    float* out = (float*)d_out;

    float *qraw, *qraw2, *kraw, *kraw2, *vraw, *vraw2, *q, *kn, *vn, *ctx;
    float *actx, *am, *al;
    cudaGetSymbolAddress((void**)&qraw,  g_qraw);
    cudaGetSymbolAddress((void**)&qraw2, g_qraw2);
    cudaGetSymbolAddress((void**)&kraw,  g_kraw);
    cudaGetSymbolAddress((void**)&kraw2, g_kraw2);
    cudaGetSymbolAddress((void**)&vraw,  g_vraw);
    cudaGetSymbolAddress((void**)&vraw2, g_vraw2);
    cudaGetSymbolAddress((void**)&q,     g_q);
    cudaGetSymbolAddress((void**)&kn,    g_kn);
    cudaGetSymbolAddress((void**)&vn,    g_vn);
    cudaGetSymbolAddress((void**)&ctx,   g_ctx);
    cudaGetSymbolAddress((void**)&actx,  g_actx);
    cudaGetSymbolAddress((void**)&am,    g_am);
    cudaGetSymbolAddress((void**)&al,    g_al);

    cudaFuncSetAttribute(attn_kernel4, cudaFuncAttributeMaxDynamicSharedMemorySize, ATT4_BYTES);
    cudaFuncSetAttribute(gemm_qkv,     cudaFuncAttributeMaxDynamicSharedMemorySize, GEMM_SMEM_BYTES);
    cudaFuncSetAttribute(gemm_out,     cudaFuncAttributeMaxDynamicSharedMemorySize, GEMM_SMEM_BYTES);

    // 1) fused QKV projection, split-K=2, 3-stage pipe
    gemm_qkv<<<dim3(48, 4, 2), 256, GEMM_SMEM_BYTES>>>(hs, Wq, Wk, Wv,
                                                       qraw, kraw, vraw, qraw2, kraw2, vraw2);

    // 2) LN + RoPE + transpose (+ split-K sum)
    lnrope_kernel<<<M_ * 48, 128>>>(qraw, qraw2, kraw, kraw2, vraw, vraw2,
                                    qlw, qlb, klw, klb, pos, q, kn, vn);

    // 3) attention: loader-converted tf32, 1 barrier/chunk, KV-split 2; then merge
    attn_kernel4<<<dim3(B_ * NH_, 2), 128, ATT4_BYTES>>>(pk, pv, mask, q, kn, vn, actx, am, al);
    attn_merge<<<dim3(B_ * NH_, 16), 128>>>(actx, am, al, ctx);

    // 4) output projection: split-K=2, 3-stage pipe, atomic accumulate
    cudaMemsetAsync(out, 0, (size_t)M_ * H_ * sizeof(float));
    gemm_out<<<dim3(32, 4, 2), 256, GEMM_SMEM_BYTES>>>(ctx, Wo, out);
}

// round 11
// speedup vs baseline: 1.0992x; 1.0992x over previous
#include <cuda_runtime.h>
#include <math.h>

#define B_   4
#define Q_   64
#define H_   4096
#define NH_  32
#define KVH_ 8
#define HD_  128
#define P_   4096
#define M_   256            // B*Q
#define KVLEN 4160          // P+Q

// ---------------- scratch ----------------
__device__ float g_qraw [M_ * NH_ * HD_];
__device__ float g_qraw2[M_ * NH_ * HD_];
__device__ float g_kraw [M_ * KVH_ * HD_];
__device__ float g_kraw2[M_ * KVH_ * HD_];
__device__ float g_vraw [M_ * KVH_ * HD_];
__device__ float g_vraw2[M_ * KVH_ * HD_];
__device__ float g_q  [B_ * NH_ * Q_ * HD_];
__device__ float g_kn [B_ * KVH_ * Q_ * HD_];
__device__ float g_vn [B_ * KVH_ * Q_ * HD_];
__device__ float g_ctx[M_ * NH_ * HD_];
__device__ float g_actx[2 * B_ * NH_ * Q_ * HD_];
__device__ float g_am  [2 * B_ * NH_ * Q_];
__device__ float g_al  [2 * B_ * NH_ * Q_];

// ---------------- tf32 helpers ----------------
__device__ __forceinline__ unsigned f2u_tf32(float x) {
    unsigned r; asm("cvt.rna.tf32.f32 %0, %1;" : "=r"(r) : "f"(x)); return r;
}
__device__ __forceinline__ float f_tf32(float x) { return __uint_as_float(f2u_tf32(x)); }
__device__ __forceinline__ unsigned fu(float x) { return __float_as_uint(x); }
__device__ __forceinline__ unsigned rna_u(unsigned x) {
    unsigned r; asm("cvt.rna.tf32.f32 %0, %1;" : "=r"(r) : "f"(__uint_as_float(x))); return r;
}

__device__ __forceinline__ void mma_tf32(float& c0, float& c1, float& c2, float& c3,
                                         unsigned a0, unsigned a1, unsigned a2, unsigned a3,
                                         unsigned b0, unsigned b1) {
    asm volatile(
        "mma.sync.aligned.m16n8k8.row.col.f32.tf32.tf32.f32 "
        "{%0,%1,%2,%3}, {%4,%5,%6,%7}, {%8,%9}, {%0,%1,%2,%3};\n"
        : "+f"(c0), "+f"(c1), "+f"(c2), "+f"(c3)
        : "r"(a0), "r"(a1), "r"(a2), "r"(a3), "r"(b0), "r"(b1));
}

__device__ __forceinline__ void cp16(void* smem_dst, const void* gmem_src) {
    unsigned ds = (unsigned)__cvta_generic_to_shared(smem_dst);
    asm volatile("cp.async.cg.shared.global [%0], [%1], 16;\n" :: "r"(ds), "l"(gmem_src));
}

// ================= pipelined tf32 GEMM: BM64 x BN128 x BK32, 256 thr, 3-stage =================
#define GA_S 36
#define GB_S 136
#define G_STAGE_FLOATS (64 * GA_S + 32 * GB_S)       // 6656
#define GEMM_SMEM_FLOATS (3 * G_STAGE_FLOATS)        // 19968
#define GEMM_SMEM_BYTES  (GEMM_SMEM_FLOATS * 4)      // 79872

__device__ __forceinline__ void gemm_issue(
    const float* __restrict__ Abase, const float* __restrict__ Wbase,
    int lda, int N, int k0, float* sA, float* sB,
    int arow, int ac4, int brow, int bc4)
{
    cp16(sA + arow * GA_S + ac4,        Abase + arow * lda + k0 + ac4);
    cp16(sA + (arow + 32) * GA_S + ac4, Abase + (arow + 32) * lda + k0 + ac4);
    #pragma unroll
    for (int i = 0; i < 4; i++)
        cp16(sB + (brow + (i << 3)) * GB_S + bc4, Wbase + (k0 + brow + (i << 3)) * N + bc4);
    asm volatile("cp.async.commit_group;\n");
}

template<bool ATOMIC>
__device__ __forceinline__ void gemm_pipe(
    const float* __restrict__ A, int lda,
    const float* __restrict__ W, float* __restrict__ C,
    int N, int kLen, int m0, int n0, float* sm)
{
    float* sAs[3] = { sm, sm + G_STAGE_FLOATS, sm + 2 * G_STAGE_FLOATS };
    float* sBs[3] = { sm + 64 * GA_S, sm + G_STAGE_FLOATS + 64 * GA_S,
                      sm + 2 * G_STAGE_FLOATS + 64 * GA_S };

    const int tid = threadIdx.x;
    const int warp = tid >> 5, lane = tid & 31;
    const int mw = warp >> 2, nw = warp & 3;
    const int g = lane >> 2, t = lane & 3;

    const int arow = tid >> 3, ac4 = (tid & 7) << 2;
    const int brow = tid >> 5, bc4 = (tid & 31) << 2;

    const float* Abase = A + m0 * lda;
    const float* Wbase = W + n0;

    float acc[2][4][4];
    #pragma unroll
    for (int mt = 0; mt < 2; mt++)
        #pragma unroll
        for (int nt = 0; nt < 4; nt++)
            #pragma unroll
            for (int i = 0; i < 4; i++) acc[mt][nt][i] = 0.f;

    const int ntiles = kLen >> 5;
    gemm_issue(Abase, Wbase, lda, N, 0,  sAs[0], sBs[0], arow, ac4, brow, bc4);
    gemm_issue(Abase, Wbase, lda, N, 32, sAs[1], sBs[1], arow, ac4, brow, bc4);

    for (int tI = 0; tI < ntiles; tI++) {
        if (tI + 2 < ntiles) {
            gemm_issue(Abase, Wbase, lda, N, (tI + 2) << 5,
                       sAs[(tI + 2) % 3], sBs[(tI + 2) % 3], arow, ac4, brow, bc4);
            asm volatile("cp.async.wait_group 2;\n");
        } else if (tI + 1 < ntiles) {
            asm volatile("cp.async.wait_group 1;\n");
        } else {
            asm volatile("cp.async.wait_group 0;\n");
        }
        __syncthreads();

        float* sA = sAs[tI % 3];
        float* sB = sBs[tI % 3];

        #pragma unroll
        for (int ks = 0; ks < 4; ks++) {
            const int k0 = ks << 3;
            unsigned a[2][4], b[4][2];
            #pragma unroll
            for (int mt = 0; mt < 2; mt++) {
                const int r = (mw << 5) + (mt << 4) + g;
                a[mt][0] = rna_u(fu(sA[r * GA_S + k0 + t]));
                a[mt][1] = rna_u(fu(sA[(r + 8) * GA_S + k0 + t]));
                a[mt][2] = rna_u(fu(sA[r * GA_S + k0 + t + 4]));
                a[mt][3] = rna_u(fu(sA[(r + 8) * GA_S + k0 + t + 4]));
            }
            #pragma unroll
            for (int nt = 0; nt < 4; nt++) {
                const int cn = (nw << 5) + (nt << 3) + g;
                b[nt][0] = rna_u(fu(sB[(k0 + t) * GB_S + cn]));
                b[nt][1] = rna_u(fu(sB[(k0 + t + 4) * GB_S + cn]));
            }
            #pragma unroll
            for (int mt = 0; mt < 2; mt++)
                #pragma unroll
                for (int nt = 0; nt < 4; nt++)
                    mma_tf32(acc[mt][nt][0], acc[mt][nt][1], acc[mt][nt][2], acc[mt][nt][3],
                             a[mt][0], a[mt][1], a[mt][2], a[mt][3], b[nt][0], b[nt][1]);
        }
        __syncthreads();
    }

    #pragma unroll
    for (int mt = 0; mt < 2; mt++) {
        const int r = m0 + (mw << 5) + (mt << 4) + g;
        #pragma unroll
        for (int nt = 0; nt < 4; nt++) {
            const int cn = n0 + (nw << 5) + (nt << 3) + (t << 1);
            if (ATOMIC) {
                atomicAdd(C + r * N + cn,           acc[mt][nt][0]);
                atomicAdd(C + r * N + cn + 1,       acc[mt][nt][1]);
                atomicAdd(C + (r + 8) * N + cn,     acc[mt][nt][2]);
                atomicAdd(C + (r + 8) * N + cn + 1, acc[mt][nt][3]);
            } else {
                *(float2*)(C + r * N + cn)       = make_float2(acc[mt][nt][0], acc[mt][nt][1]);
                *(float2*)(C + (r + 8) * N + cn) = make_float2(acc[mt][nt][2], acc[mt][nt][3]);
            }
        }
    }
}

// fused QKV projection, split-K = 2 (partials summed in lnrope)
__global__ __launch_bounds__(256, 2) void gemm_qkv(
    const float* __restrict__ hs,
    const float* __restrict__ Wq, const float* __restrict__ Wk, const float* __restrict__ Wv,
    float* __restrict__ qraw, float* __restrict__ kraw, float* __restrict__ vraw,
    float* __restrict__ qraw2, float* __restrict__ kraw2, float* __restrict__ vraw2)
{
    extern __shared__ float smg[];
    const int x = blockIdx.x;
    const int kw = blockIdx.z;
    const float* W; float* C; int N, nb;
    if (x < 32)      { W = Wq; C = kw ? qraw2 : qraw; N = 4096; nb = x; }
    else if (x < 40) { W = Wk; C = kw ? kraw2 : kraw; N = 1024; nb = x - 32; }
    else             { W = Wv; C = kw ? vraw2 : vraw; N = 1024; nb = x - 40; }
    gemm_pipe<false>(hs + kw * 2048, H_, W + kw * 2048 * N, C, N, 2048,
                     blockIdx.y << 6, nb << 7, smg);
}

// out projection, split-K = 2, atomic accumulate into pre-zeroed out
__global__ __launch_bounds__(256, 2) void gemm_out(
    const float* __restrict__ A, const float* __restrict__ W, float* __restrict__ out)
{
    extern __shared__ float smg[];
    const int kw = blockIdx.z;
    const int KH = (NH_ * HD_) / 2;
    gemm_pipe<true>(A + kw * KH, NH_ * HD_, W + kw * KH * H_, out,
                    H_, KH, blockIdx.y << 6, blockIdx.x << 7, smg);
}

// ---------------- LN + RoPE + transpose (sums split-K partials) ----------------
__global__ __launch_bounds__(128) void lnrope_kernel(
    const float* __restrict__ qraw, const float* __restrict__ qraw2,
    const float* __restrict__ kraw, const float* __restrict__ kraw2,
    const float* __restrict__ vraw, const float* __restrict__ vraw2,
    const float* __restrict__ qlw, const float* __restrict__ qlb,
    const float* __restrict__ klw, const float* __restrict__ klb,
    const int* __restrict__ pos_ids,
    float* __restrict__ qout, float* __restrict__ knout, float* __restrict__ vnout)
{
    const int blk = blockIdx.x;
    const int bq = blk / 48;
    const int t  = blk - bq * 48;
    const int b  = bq >> 6, qi = bq & 63;
    const int d  = threadIdx.x;

    if (t >= 40) {
        const int vh = t - 40;
        const int i = bq * (KVH_ * HD_) + vh * HD_ + d;
        vnout[((b * KVH_ + vh) * Q_ + qi) * HD_ + d] = vraw[i] + vraw2[i];
        return;
    }

    __shared__ float row[128];
    __shared__ float red[4];

    float x, w, bb;
    const bool isq = (t < 32);
    if (isq) {
        const int i = bq * (NH_ * HD_) + t * HD_ + d;
        x  = qraw[i] + qraw2[i];
        w  = qlw[t * HD_ + d];
        bb = qlb[t * HD_ + d];
    } else {
        const int kh = t - 32;
        const int i = bq * (KVH_ * HD_) + kh * HD_ + d;
        x  = kraw[i] + kraw2[i];
        w  = klw[kh * HD_ + d];
        bb = klb[kh * HD_ + d];
    }

    const int lane = d & 31, wid = d >> 5;

    float s = x;
    #pragma unroll
    for (int o = 16; o; o >>= 1) s += __shfl_xor_sync(0xffffffffu, s, o);
    if (lane == 0) red[wid] = s;
    __syncthreads();
    const float mean = (red[0] + red[1] + red[2] + red[3]) * (1.f / 128.f);
    const float dx = x - mean;
    float s2 = dx * dx;
    __syncthreads();
    #pragma unroll
    for (int o = 16; o; o >>= 1) s2 += __shfl_xor_sync(0xffffffffu, s2, o);
    if (lane == 0) red[wid] = s2;
    __syncthreads();
    const float var = (red[0] + red[1] + red[2] + red[3]) * (1.f / 128.f);

    const float xn = dx * rsqrtf(var + 1e-5f) * w + bb;
    row[d] = xn;
    __syncthreads();
    const float partner = row[d ^ 64];

    const int j = d & 63;
    const float inv = (float)exp(-(double)(2 * j) * (1.0 / 128.0) * 9.210340371976184);
    const float ang = (float)pos_ids[b * Q_ + qi] * inv;
    const float c = cosf(ang), sn = sinf(ang);
    const float rot = (d < 64) ? -partner : partner;
    const float outv = xn * c + rot * sn;

    if (isq)
        qout[((b * NH_ + t) * Q_ + qi) * HD_ + d] = outv * 0.08838834764831845f;
    else
        knout[((b * KVH_ + (t - 32)) * Q_ + qi) * HD_ + d] = outv;
}

// ---------------- flash attention v5: R9 base + Q fragments hoisted to registers ----------------
// grid = (B*NH, 2), 128 threads = 4 warps. chunk=32, KV split=2 (2080 keys = 65 chunks).
#define CHK   32
#define NCHK  65
#define SPLIT_KEYS 2080
#define SQ_S  132
#define SKV_S 132
#define SS2_S 36
#define AOFF_Q   0
#define AOFF_K0  (64 * SQ_S)                 // 8448
#define AOFF_K1  (AOFF_K0 + CHK * SKV_S)     // 12672
#define AOFF_V0  (AOFF_K1 + CHK * SKV_S)     // 16896
#define AOFF_V1  (AOFF_V0 + CHK * SKV_S)     // 21120
#define AOFF_S   (AOFF_V1 + CHK * SKV_S)     // 25344
#define ATT5_FLOATS (AOFF_S + 64 * SS2_S)    // 27648
#define ATT5_BYTES  (ATT5_FLOATS * 4)        // 110592

__global__ __launch_bounds__(128, 2) void attn_kernel5(
    const float* __restrict__ past_k, const float* __restrict__ past_v,
    const float* __restrict__ mask,
    const float* __restrict__ qg, const float* __restrict__ kn,
    const float* __restrict__ vn,
    float* __restrict__ actx, float* __restrict__ am, float* __restrict__ al)
{
    extern __shared__ float sm[];
    float* sQ  = sm + AOFF_Q;
    float* sKb[2] = { sm + AOFF_K0, sm + AOFF_K1 };
    float* sVb[2] = { sm + AOFF_V0, sm + AOFF_V1 };
    float* sS  = sm + AOFF_S;

    const int tid = threadIdx.x;
    const int bh = blockIdx.x;           // b*32 + h
    const int split = blockIdx.y;
    const int b = bh >> 5;
    const int h = bh & 31;
    const int kvh = h >> 2;

    const int warp = tid >> 5, lane = tid & 31;
    const int g = lane >> 2, t = lane & 3;
    const int r0 = (warp << 4) + g;      // first owned row; second is r0+8

    const int lrow = tid >> 5, lc4 = (tid & 31) << 2;   // loader: 4 rows per pass

    // ---- load Q (tf32-rounded, row-major) ----
    const float* qbase = qg + (b * NH_ + h) * Q_ * HD_;
    #pragma unroll
    for (int i = 0; i < 16; i++) {
        const int row = lrow + (i << 2);
        const float4 v = *(const float4*)(qbase + row * HD_ + lc4);
        float* p = sQ + row * SQ_S + lc4;
        p[0] = f_tf32(v.x); p[1] = f_tf32(v.y); p[2] = f_tf32(v.z); p[3] = f_tf32(v.w);
    }

    // online softmax state in registers
    float m0r = -1e30f, m1r = -1e30f, l0r = 0.f, l1r = 0.f;

    float o[16][4];
    #pragma unroll
    for (int nt = 0; nt < 16; nt++)
        #pragma unroll
        for (int i = 0; i < 4; i++) o[nt][i] = 0.f;

    const int kvoff  = ((b * KVH_ + kvh) * P_) * HD_;
    const int newoff = (b * KVH_ + kvh) * Q_ * HD_;
    const int keybase0 = split * SPLIT_KEYS;

    // prologue: issue chunk 0
    {
        const int base = keybase0;
        const float* Kc = (base < P_) ? past_k + kvoff + base * HD_ : kn + newoff + (base - P_) * HD_;
        const float* Vc = (base < P_) ? past_v + kvoff + base * HD_ : vn + newoff + (base - P_) * HD_;
        #pragma unroll
        for (int i = 0; i < 8; i++) {
            const int row = lrow + (i << 2);
            cp16(sKb[0] + row * SKV_S + lc4, Kc + row * HD_ + lc4);
            cp16(sVb[0] + row * SKV_S + lc4, Vc + row * HD_ + lc4);
        }
        asm volatile("cp.async.commit_group;\n");
    }

    // ---- hoist Q fragments into registers (invariant across all 65 chunks) ----
    __syncthreads();
    unsigned qa[16][4];
    #pragma unroll
    for (int ks = 0; ks < 16; ks++) {
        const int k0 = ks << 3;
        qa[ks][0] = fu(sQ[r0 * SQ_S + k0 + t]);
        qa[ks][1] = fu(sQ[(r0 + 8) * SQ_S + k0 + t]);
        qa[ks][2] = fu(sQ[r0 * SQ_S + k0 + t + 4]);
        qa[ks][3] = fu(sQ[(r0 + 8) * SQ_S + k0 + t + 4]);
    }

    for (int chunk = 0; chunk < NCHK; chunk++) {
        if (chunk + 1 < NCHK) {
            const int base = keybase0 + (chunk + 1) * CHK;
            const float* Kc = (base < P_) ? past_k + kvoff + base * HD_ : kn + newoff + (base - P_) * HD_;
            const float* Vc = (base < P_) ? past_v + kvoff + base * HD_ : vn + newoff + (base - P_) * HD_;
            float* dK = sKb[(chunk + 1) & 1];
            float* dV = sVb[(chunk + 1) & 1];
            #pragma unroll
            for (int i = 0; i < 8; i++) {
                const int row = lrow + (i << 2);
                cp16(dK + row * SKV_S + lc4, Kc + row * HD_ + lc4);
                cp16(dV + row * SKV_S + lc4, Vc + row * HD_ + lc4);
            }
            asm volatile("cp.async.commit_group;\n");
            asm volatile("cp.async.wait_group 1;\n");
        } else {
            asm volatile("cp.async.wait_group 0;\n");
        }
        __syncthreads();

        float* sK = sKb[chunk & 1];
        float* sV = sVb[chunk & 1];

        // ---- S = Q K^T : warp tile 16x32, Q frags from registers ----
        float sc[4][4];
        #pragma unroll
        for (int nt = 0; nt < 4; nt++)
            #pragma unroll
            for (int i = 0; i < 4; i++) sc[nt][i] = 0.f;

        #pragma unroll
        for (int ks = 0; ks < 16; ks++) {
            const int k0 = ks << 3;
            #pragma unroll
            for (int nt = 0; nt < 4; nt++) {
                const int cn = (nt << 3) + g;
                unsigned b0 = rna_u(fu(sK[cn * SKV_S + k0 + t]));
                unsigned b1 = rna_u(fu(sK[cn * SKV_S + k0 + t + 4]));
                mma_tf32(sc[nt][0], sc[nt][1], sc[nt][2], sc[nt][3],
                         qa[ks][0], qa[ks][1], qa[ks][2], qa[ks][3], b0, b1);
            }
        }

        // ---- mask (whole chunk masked iff base >= P_; split boundary aligns) ----
        const int base = keybase0 + chunk * CHK;
        if (base >= P_) {
            const float* mr0 = mask + (b * Q_ + r0) * KVLEN + base;
            const float* mr1 = mask + (b * Q_ + r0 + 8) * KVLEN + base;
            #pragma unroll
            for (int nt = 0; nt < 4; nt++) {
                const float2 mv0 = *(const float2*)(mr0 + (nt << 3) + (t << 1));
                const float2 mv1 = *(const float2*)(mr1 + (nt << 3) + (t << 1));
                sc[nt][0] += mv0.x; sc[nt][1] += mv0.y;
                sc[nt][2] += mv1.x; sc[nt][3] += mv1.y;
            }
        }

        // ---- register softmax ----
        float cm0 = -1e30f, cm1 = -1e30f;
        #pragma unroll
        for (int nt = 0; nt < 4; nt++) {
            cm0 = fmaxf(cm0, fmaxf(sc[nt][0], sc[nt][1]));
            cm1 = fmaxf(cm1, fmaxf(sc[nt][2], sc[nt][3]));
        }
        cm0 = fmaxf(cm0, __shfl_xor_sync(0xffffffffu, cm0, 1));
        cm0 = fmaxf(cm0, __shfl_xor_sync(0xffffffffu, cm0, 2));
        cm1 = fmaxf(cm1, __shfl_xor_sync(0xffffffffu, cm1, 1));
        cm1 = fmaxf(cm1, __shfl_xor_sync(0xffffffffu, cm1, 2));

        const float mn0 = fmaxf(m0r, cm0);
        const float mn1 = fmaxf(m1r, cm1);
        const float scl0 = __expf(m0r - mn0);
        const float scl1 = __expf(m1r - mn1);

        float sum0 = 0.f, sum1 = 0.f;
        #pragma unroll
        for (int nt = 0; nt < 4; nt++) {
            float p;
            p = f_tf32(__expf(sc[nt][0] - mn0)); sc[nt][0] = p; sum0 += p;
            p = f_tf32(__expf(sc[nt][1] - mn0)); sc[nt][1] = p; sum0 += p;
            p = f_tf32(__expf(sc[nt][2] - mn1)); sc[nt][2] = p; sum1 += p;
            p = f_tf32(__expf(sc[nt][3] - mn1)); sc[nt][3] = p; sum1 += p;
        }
        sum0 += __shfl_xor_sync(0xffffffffu, sum0, 1);
        sum0 += __shfl_xor_sync(0xffffffffu, sum0, 2);
        sum1 += __shfl_xor_sync(0xffffffffu, sum1, 1);
        sum1 += __shfl_xor_sync(0xffffffffu, sum1, 2);

        l0r = l0r * scl0 + sum0;  m0r = mn0;
        l1r = l1r * scl1 + sum1;  m1r = mn1;

        // ---- rescale ctx frags ----
        #pragma unroll
        for (int nt = 0; nt < 16; nt++) {
            o[nt][0] *= scl0; o[nt][1] *= scl0;
            o[nt][2] *= scl1; o[nt][3] *= scl1;
        }

        // ---- store P to smem (warp-local rows) ----
        #pragma unroll
        for (int nt = 0; nt < 4; nt++) {
            *(float2*)(sS + r0 * SS2_S + (nt << 3) + (t << 1))       = make_float2(sc[nt][0], sc[nt][1]);
            *(float2*)(sS + (r0 + 8) * SS2_S + (nt << 3) + (t << 1)) = make_float2(sc[nt][2], sc[nt][3]);
        }
        __syncwarp();

        // ---- ctx += P @ V : warp tile 16x128, k=32 ----
        #pragma unroll
        for (int ks = 0; ks < 4; ks++) {
            const int k0 = ks << 3;
            unsigned a0 = fu(sS[r0 * SS2_S + k0 + t]);
            unsigned a1 = fu(sS[(r0 + 8) * SS2_S + k0 + t]);
            unsigned a2 = fu(sS[r0 * SS2_S + k0 + t + 4]);
            unsigned a3 = fu(sS[(r0 + 8) * SS2_S + k0 + t + 4]);
            #pragma unroll
            for (int nt = 0; nt < 16; nt++) {
                const int cn = (nt << 3) + g;
                unsigned b0 = rna_u(fu(sV[(k0 + t) * SKV_S + cn]));
                unsigned b1 = rna_u(fu(sV[(k0 + t + 4) * SKV_S + cn]));
                mma_tf32(o[nt][0], o[nt][1], o[nt][2], o[nt][3], a0, a1, a2, a3, b0, b1);
            }
        }
        __syncthreads();
    }

    // ---- epilogue: write unnormalized acc + (m, l) ----
    float* abase = actx + ((size_t)(split * (B_ * NH_) + bh) * Q_) * HD_;
    #pragma unroll
    for (int nt = 0; nt < 16; nt++) {
        const int cn = (nt << 3) + (t << 1);
        *(float2*)(abase + r0 * HD_ + cn)       = make_float2(o[nt][0], o[nt][1]);
        *(float2*)(abase + (r0 + 8) * HD_ + cn) = make_float2(o[nt][2], o[nt][3]);
    }
    if (t == 0) {
        const int sidx = (split * (B_ * NH_) + bh) * Q_;
        am[sidx + r0]     = m0r;  al[sidx + r0]     = l0r;
        am[sidx + r0 + 8] = m1r;  al[sidx + r0 + 8] = l1r;
    }
}

// merge the two attention splits -> ctx[b][qi][h][d]
__global__ __launch_bounds__(128) void attn_merge(
    const float* __restrict__ actx, const float* __restrict__ am,
    const float* __restrict__ al, float* __restrict__ ctx)
{
    const int bh = blockIdx.x;
    const int b = bh >> 5, h = bh & 31;
    const int d = threadIdx.x;
    const int q0 = blockIdx.y << 2;

    #pragma unroll
    for (int k = 0; k < 4; k++) {
        const int qi = q0 + k;
        const float m0 = am[bh * Q_ + qi];
        const float m1 = am[(B_ * NH_ + bh) * Q_ + qi];
        const float mm = fmaxf(m0, m1);
        const float w0 = __expf(m0 - mm), w1 = __expf(m1 - mm);
        const float den = w0 * al[bh * Q_ + qi] + w1 * al[(B_ * NH_ + bh) * Q_ + qi];
        const float inv = 1.0f / den;
        const float a0 = actx[((size_t)bh * Q_ + qi) * HD_ + d];
        const float a1 = actx[((size_t)(B_ * NH_ + bh) * Q_ + qi) * HD_ + d];
        ctx[((b * Q_ + qi) * NH_ + h) * HD_ + d] = (w0 * a0 + w1 * a1) * inv;
    }
}

// ---------------- launch ----------------
extern "C" void kernel_launch(void* const* d_in, const int* in_sizes, int n_in,
                              void* d_out, int out_size)
{
    const float* hs   = (const float*)d_in[0];
    const float* Wq   = (const float*)d_in[1];
    const float* Wk   = (const float*)d_in[2];
    const float* Wv   = (const float*)d_in[3];
    const float* Wo   = (const float*)d_in[4];
    const float* qlw  = (const float*)d_in[5];
    const float* qlb  = (const float*)d_in[6];
    const float* klw  = (const float*)d_in[7];
    const float* klb  = (const float*)d_in[8];
    const float* pk   = (const float*)d_in[9];
    const float* pv   = (const float*)d_in[10];
    const float* mask = (const float*)d_in[11];
    const int*   pos  = (const int*)d_in[12];
    float* out = (float*)d_out;

    float *qraw, *qraw2, *kraw, *kraw2, *vraw, *vraw2, *q, *kn, *vn, *ctx;
    float *actx, *am, *al;
    cudaGetSymbolAddress((void**)&qraw,  g_qraw);
    cudaGetSymbolAddress((void**)&qraw2, g_qraw2);
    cudaGetSymbolAddress((void**)&kraw,  g_kraw);
    cudaGetSymbolAddress((void**)&kraw2, g_kraw2);
    cudaGetSymbolAddress((void**)&vraw,  g_vraw);
    cudaGetSymbolAddress((void**)&vraw2, g_vraw2);
    cudaGetSymbolAddress((void**)&q,     g_q);
    cudaGetSymbolAddress((void**)&kn,    g_kn);
    cudaGetSymbolAddress((void**)&vn,    g_vn);
    cudaGetSymbolAddress((void**)&ctx,   g_ctx);
    cudaGetSymbolAddress((void**)&actx,  g_actx);
    cudaGetSymbolAddress((void**)&am,    g_am);
    cudaGetSymbolAddress((void**)&al,    g_al);

    cudaFuncSetAttribute(attn_kernel5, cudaFuncAttributeMaxDynamicSharedMemorySize, ATT5_BYTES);
    cudaFuncSetAttribute(gemm_qkv,     cudaFuncAttributeMaxDynamicSharedMemorySize, GEMM_SMEM_BYTES);
    cudaFuncSetAttribute(gemm_out,     cudaFuncAttributeMaxDynamicSharedMemorySize, GEMM_SMEM_BYTES);

    // 1) fused QKV projection, split-K=2, 3-stage pipe
    gemm_qkv<<<dim3(48, 4, 2), 256, GEMM_SMEM_BYTES>>>(hs, Wq, Wk, Wv,
                                                       qraw, kraw, vraw, qraw2, kraw2, vraw2);

    // 2) LN + RoPE + transpose (+ split-K sum)
    lnrope_kernel<<<M_ * 48, 128>>>(qraw, qraw2, kraw, kraw2, vraw, vraw2,
                                    qlw, qlb, klw, klb, pos, q, kn, vn);

    // 3) attention: R9 base + hoisted Q frags, KV-split 2; then merge
    attn_kernel5<<<dim3(B_ * NH_, 2), 128, ATT5_BYTES>>>(pk, pv, mask, q, kn, vn, actx, am, al);
    attn_merge<<<dim3(B_ * NH_, 16), 128>>>(actx, am, al, ctx);

    // 4) output projection: split-K=2, 3-stage pipe, atomic accumulate
    cudaMemsetAsync(out, 0, (size_t)M_ * H_ * sizeof(float));
    gemm_out<<<dim3(32, 4, 2), 256, GEMM_SMEM_BYTES>>>(ctx, Wo, out);
}